// round 1
// baseline (speedup 1.0000x reference)
#include <cuda_runtime.h>
#include <math.h>

// Problem constants
#define BB 2
#define NN 384
#define DD 128
#define VV 8192
#define LL 2
#define NPAIR 73920          // N*(N+1)/2
#define TILES_PER_B 4620     // NPAIR / 16  (exact)
#define NTILES 9240          // 2 batches
#define PA_GRID 148

// ---------------- scratch (device globals; no allocation) ----------------
__device__ float g_x[BB * NN * DD];            // activations [B,N,128]
__device__ float g_a[BB * NN * 256];           // x @ W1[:128]  + b1
__device__ float g_c[BB * NN * 256];           // x @ W1[128:]
__device__ float g_h[BB * NN * 512];           // FFN intermediate
__device__ float g_y[BB * NN * DD];            // FFN output
__device__ float g_p[(size_t)BB * NN * NN * DD]; // pair vectors (j<=i only)
__device__ float g_s[BB * NN * NN];            // pair norms

__device__ __forceinline__ float gelu_exact(float x) {
    return 0.5f * x * (1.0f + erff(x * 0.7071067811865475244f));
}

// ---------------- embedding ----------------
__global__ void embed_kernel(const int* __restrict__ ids,
                             const float* __restrict__ emb,
                             const float* __restrict__ pos) {
    int t = blockIdx.x * blockDim.x + threadIdx.x;
    if (t >= BB * NN * DD) return;
    int d = t & (DD - 1);
    int bn = t >> 7;
    int n = bn % NN;
    g_x[t] = emb[ids[bn] * DD + d] + pos[n * DD + d];
}

// ---------------- generic 64x64x16 fp32 GEMM: C = act(A@W + bias) -------
// All M,N divisible by 64, K divisible by 16 in this model (768, {128,256,512,8192}).
template <int ACT>
__global__ __launch_bounds__(256) void gemm64(
    const float* __restrict__ A, const float* __restrict__ W,
    const float* __restrict__ bias, float* __restrict__ C,
    int K, int ldA, int ldW, int ldC) {
    __shared__ float As[16][64];
    __shared__ float Ws[16][64];
    const int bm = blockIdx.y * 64;
    const int bn = blockIdx.x * 64;
    const int tid = threadIdx.x;

    const int ar = tid >> 2;          // 0..63
    const int ak = (tid & 3) * 4;     // 0,4,8,12
    const int wk = tid >> 4;          // 0..15
    const int wn = (tid & 15) * 4;    // 0..60
    const int tm = (tid >> 4) * 4;    // 0..60
    const int tn = (tid & 15) * 4;    // 0..60

    float acc[4][4] = {};
    for (int k0 = 0; k0 < K; k0 += 16) {
        float4 av = *(const float4*)&A[(size_t)(bm + ar) * ldA + k0 + ak];
        As[ak + 0][ar] = av.x;
        As[ak + 1][ar] = av.y;
        As[ak + 2][ar] = av.z;
        As[ak + 3][ar] = av.w;
        *(float4*)&Ws[wk][wn] = *(const float4*)&W[(size_t)(k0 + wk) * ldW + bn + wn];
        __syncthreads();
#pragma unroll
        for (int k = 0; k < 16; k++) {
            float4 a = *(const float4*)&As[k][tm];
            float4 w = *(const float4*)&Ws[k][tn];
            acc[0][0] += a.x * w.x; acc[0][1] += a.x * w.y; acc[0][2] += a.x * w.z; acc[0][3] += a.x * w.w;
            acc[1][0] += a.y * w.x; acc[1][1] += a.y * w.y; acc[1][2] += a.y * w.z; acc[1][3] += a.y * w.w;
            acc[2][0] += a.z * w.x; acc[2][1] += a.z * w.y; acc[2][2] += a.z * w.z; acc[2][3] += a.z * w.w;
            acc[3][0] += a.w * w.x; acc[3][1] += a.w * w.y; acc[3][2] += a.w * w.z; acc[3][3] += a.w * w.w;
        }
        __syncthreads();
    }
    float4 bv = make_float4(0.f, 0.f, 0.f, 0.f);
    if (bias) bv = *(const float4*)&bias[bn + tn];
#pragma unroll
    for (int r = 0; r < 4; r++) {
        float4 o;
        o.x = acc[r][0] + bv.x;
        o.y = acc[r][1] + bv.y;
        o.z = acc[r][2] + bv.z;
        o.w = acc[r][3] + bv.w;
        if (ACT == 1) {
            o.x = gelu_exact(o.x); o.y = gelu_exact(o.y);
            o.z = gelu_exact(o.z); o.w = gelu_exact(o.w);
        }
        *(float4*)&C[(size_t)(bm + tm + r) * ldC + bn + tn] = o;
    }
}

// ---------------- pair phase A: per pair (j<=i) compute p vector + norm ----
// Persistent CTAs, W2(128KB)+W3(64KB) cached in smem once, 16 pairs per tile.
#define PA_SMEM_FLOATS 55552
#define PA_SMEM_BYTES (PA_SMEM_FLOATS * 4)

__global__ __launch_bounds__(256, 1) void pair_phaseA(
    const float* __restrict__ W2, const float* __restrict__ b2,
    const float* __restrict__ W3, const float* __restrict__ b3) {
    extern __shared__ float sm[];
    float* W2s = sm;                 // 32768
    float* W3s = sm + 32768;         // 16384
    float* b2s = sm + 49152;         // 128
    float* b3s = sm + 49280;         // 128
    float* H1s = sm + 49408;         // 16*256
    float* H2s = sm + 53504;         // 16*128
    __shared__ int pis[16], pjs[16];

    const int tid = threadIdx.x;
    for (int idx = tid; idx < 32768; idx += 256) W2s[idx] = W2[idx];
    for (int idx = tid; idx < 16384; idx += 256) W3s[idx] = W3[idx];
    if (tid < 128) { b2s[tid] = b2[tid]; b3s[tid] = b3[tid]; }
    __syncthreads();

    const int cg = tid & 31;   // lane / column-group (4 cols)
    const int pg = tid >> 5;   // warp / pair-group (2 pairs)

    for (int tile = blockIdx.x; tile < NTILES; tile += gridDim.x) {
        int b = tile / TILES_PER_B;
        int tbase = (tile - b * TILES_PER_B) * 16;
        if (tid < 16) {
            int idx = tbase + tid;
            int i = (int)((sqrtf(8.0f * (float)idx + 1.0f) - 1.0f) * 0.5f);
            while ((i + 1) * (i + 2) / 2 <= idx) ++i;
            while (i * (i + 1) / 2 > idx) --i;
            pis[tid] = i;
            pjs[tid] = idx - i * (i + 1) / 2;
        }
        __syncthreads();

        // Build H1 = gelu(a_i + c_j)   (b1 already folded into a)
#pragma unroll 4
        for (int pp = 0; pp < 16; pp++) {
            const float* arow = g_a + (size_t)(b * NN + pis[pp]) * 256;
            const float* crow = g_c + (size_t)(b * NN + pjs[pp]) * 256;
            H1s[pp * 256 + tid] = gelu_exact(arow[tid] + crow[tid]);
        }
        __syncthreads();

        // GEMM1: H2[16,128] = gelu(H1[16,256] @ W2[256,128] + b2)
        float acc0[4] = {0.f, 0.f, 0.f, 0.f};
        float acc1[4] = {0.f, 0.f, 0.f, 0.f};
        {
            const float* h0p = H1s + (pg * 2) * 256;
            const float* h1p = H1s + (pg * 2 + 1) * 256;
#pragma unroll 8
            for (int k = 0; k < 256; k++) {
                float h0 = h0p[k];
                float h1 = h1p[k];
                float4 w = *(const float4*)(W2s + k * 128 + cg * 4);
                acc0[0] += h0 * w.x; acc0[1] += h0 * w.y; acc0[2] += h0 * w.z; acc0[3] += h0 * w.w;
                acc1[0] += h1 * w.x; acc1[1] += h1 * w.y; acc1[2] += h1 * w.z; acc1[3] += h1 * w.w;
            }
        }
#pragma unroll
        for (int q = 0; q < 4; q++) {
            float bq = b2s[cg * 4 + q];
            H2s[(pg * 2) * 128 + cg * 4 + q] = gelu_exact(acc0[q] + bq);
            H2s[(pg * 2 + 1) * 128 + cg * 4 + q] = gelu_exact(acc1[q] + bq);
        }
        __syncthreads();

        // GEMM2: P[16,128] = H2 @ W3 + b3
        float d0[4] = {0.f, 0.f, 0.f, 0.f};
        float d1[4] = {0.f, 0.f, 0.f, 0.f};
        {
            const float* h0p = H2s + (pg * 2) * 128;
            const float* h1p = H2s + (pg * 2 + 1) * 128;
#pragma unroll 8
            for (int k = 0; k < 128; k++) {
                float h0 = h0p[k];
                float h1 = h1p[k];
                float4 w = *(const float4*)(W3s + k * 128 + cg * 4);
                d0[0] += h0 * w.x; d0[1] += h0 * w.y; d0[2] += h0 * w.z; d0[3] += h0 * w.w;
                d1[0] += h1 * w.x; d1[1] += h1 * w.y; d1[2] += h1 * w.z; d1[3] += h1 * w.w;
            }
        }
        int i0 = pis[pg * 2], j0 = pjs[pg * 2];
        int i1 = pis[pg * 2 + 1], j1 = pjs[pg * 2 + 1];
        float4 bv = *(const float4*)(b3s + cg * 4);
        float4 o0, o1;
        o0.x = d0[0] + bv.x; o0.y = d0[1] + bv.y; o0.z = d0[2] + bv.z; o0.w = d0[3] + bv.w;
        o1.x = d1[0] + bv.x; o1.y = d1[1] + bv.y; o1.z = d1[2] + bv.z; o1.w = d1[3] + bv.w;
        *(float4*)(g_p + ((size_t)(b * NN + i0) * NN + j0) * DD + cg * 4) = o0;
        *(float4*)(g_p + ((size_t)(b * NN + i1) * NN + j1) * DD + cg * 4) = o1;

        float ss0 = o0.x * o0.x + o0.y * o0.y + o0.z * o0.z + o0.w * o0.w;
        float ss1 = o1.x * o1.x + o1.y * o1.y + o1.z * o1.z + o1.w * o1.w;
#pragma unroll
        for (int off = 16; off; off >>= 1) {
            ss0 += __shfl_xor_sync(0xffffffffu, ss0, off);
            ss1 += __shfl_xor_sync(0xffffffffu, ss1, off);
        }
        if (cg == 0) {
            g_s[(b * NN + i0) * NN + j0] = sqrtf(fmaxf(ss0, 1e-30f));
            g_s[(b * NN + i1) * NN + j1] = sqrtf(fmaxf(ss1, 1e-30f));
        }
        __syncthreads();  // protect pis/H-buffers before next iteration
    }
}

// ---------------- block-of-128 reductions ----------------
__device__ __forceinline__ float blockSum128(float v, float* red) {
    int tid = threadIdx.x;
    red[tid] = v;
    __syncthreads();
    for (int s = 64; s; s >>= 1) {
        if (tid < s) red[tid] += red[tid + s];
        __syncthreads();
    }
    float r = red[0];
    __syncthreads();
    return r;
}
__device__ __forceinline__ float blockMax128(float v, float* red) {
    int tid = threadIdx.x;
    red[tid] = v;
    __syncthreads();
    for (int s = 64; s; s >>= 1) {
        if (tid < s) red[tid] = fmaxf(red[tid], red[tid + s]);
        __syncthreads();
    }
    float r = red[0];
    __syncthreads();
    return r;
}

// ---------------- phase B: softmax over norms + weighted sum + residual + LN
__global__ __launch_bounds__(128) void pair_reduce_ln(
    const float* __restrict__ lng, const float* __restrict__ lnb) {
    __shared__ float red[128];
    const int bi = blockIdx.x;          // b*NN + i
    const int i = bi % NN;
    const int tid = threadIdx.x;
    const int np = i + 1;
    const float* srow = g_s + (size_t)bi * NN;

    float lm = -1e30f;
    for (int j = tid; j < np; j += 128) lm = fmaxf(lm, srow[j]);
    float m = blockMax128(lm, red);

    const float* prow = g_p + (size_t)bi * NN * DD;
    float acc = 0.f, den = 0.f;
#pragma unroll 4
    for (int j = 0; j < np; j++) {
        float w = expf(srow[j] - m);
        den += w;
        acc += w * prow[(size_t)j * DD + tid];
    }
    float v = g_x[bi * DD + tid] + acc / den;

    float mean = blockSum128(v, red) * (1.0f / DD);
    float dv = v - mean;
    float var = blockSum128(dv * dv, red) * (1.0f / DD);
    g_x[bi * DD + tid] = dv * rsqrtf(var + 1e-5f) * lng[tid] + lnb[tid];
}

// ---------------- FFN residual + LN ----------------
__global__ __launch_bounds__(128) void add_ln(
    const float* __restrict__ lng, const float* __restrict__ lnb) {
    __shared__ float red[128];
    const int bi = blockIdx.x;
    const int tid = threadIdx.x;
    float v = g_x[bi * DD + tid] + g_y[bi * DD + tid];
    float mean = blockSum128(v, red) * (1.0f / DD);
    float dv = v - mean;
    float var = blockSum128(dv * dv, red) * (1.0f / DD);
    g_x[bi * DD + tid] = dv * rsqrtf(var + 1e-5f) * lng[tid] + lnb[tid];
}

// ---------------- launcher ----------------
extern "C" void kernel_launch(void* const* d_in, const int* in_sizes, int n_in,
                              void* d_out, int out_size) {
    const int* ids = (const int*)d_in[0];
    const float* embw = (const float*)d_in[1];
    const float* pos = (const float*)d_in[2];
    const float* pW1 = (const float*)d_in[3];
    const float* pb1 = (const float*)d_in[4];
    const float* pW2 = (const float*)d_in[5];
    const float* pb2 = (const float*)d_in[6];
    const float* pW3 = (const float*)d_in[7];
    const float* pb3 = (const float*)d_in[8];
    const float* ln1g = (const float*)d_in[9];
    const float* ln1b = (const float*)d_in[10];
    const float* fW1 = (const float*)d_in[11];
    const float* fb1 = (const float*)d_in[12];
    const float* fW2 = (const float*)d_in[13];
    const float* fb2 = (const float*)d_in[14];
    const float* ln2g = (const float*)d_in[15];
    const float* ln2b = (const float*)d_in[16];
    const float* headW = (const float*)d_in[17];
    const float* headb = (const float*)d_in[18];
    float* out = (float*)d_out;

    cudaFuncSetAttribute(pair_phaseA, cudaFuncAttributeMaxDynamicSharedMemorySize,
                         PA_SMEM_BYTES);

    float *xp, *ap, *cp, *hp, *yp;
    cudaGetSymbolAddress((void**)&xp, g_x);
    cudaGetSymbolAddress((void**)&ap, g_a);
    cudaGetSymbolAddress((void**)&cp, g_c);
    cudaGetSymbolAddress((void**)&hp, g_h);
    cudaGetSymbolAddress((void**)&yp, g_y);

    embed_kernel<<<(BB * NN * DD + 255) / 256, 256>>>(ids, embw, pos);

    for (int l = 0; l < LL; l++) {
        // A = x @ W1[:128,:] + b1   -> g_a [768,256]
        gemm64<0><<<dim3(256 / 64, 768 / 64), 256>>>(
            xp, pW1 + (size_t)l * 256 * 256, pb1 + l * 256, ap, 128, 128, 256, 256);
        // C = x @ W1[128:,:]        -> g_c [768,256]
        gemm64<0><<<dim3(256 / 64, 768 / 64), 256>>>(
            xp, pW1 + (size_t)l * 256 * 256 + 128 * 256, nullptr, cp, 128, 128, 256, 256);
        // pair vectors + norms
        pair_phaseA<<<PA_GRID, 256, PA_SMEM_BYTES>>>(
            pW2 + (size_t)l * 256 * 128, pb2 + l * 128,
            pW3 + (size_t)l * 128 * 128, pb3 + l * 128);
        // softmax-weighted reduce + residual + LN1
        pair_reduce_ln<<<BB * NN, 128>>>(ln1g + l * 128, ln1b + l * 128);
        // FFN
        gemm64<1><<<dim3(512 / 64, 768 / 64), 256>>>(
            xp, fW1 + (size_t)l * 128 * 512, fb1 + l * 512, hp, 128, 128, 512, 512);
        gemm64<0><<<dim3(128 / 64, 768 / 64), 256>>>(
            hp, fW2 + (size_t)l * 512 * 128, fb2 + l * 128, yp, 512, 512, 128, 128);
        add_ln<<<BB * NN, 128>>>(ln2g + l * 128, ln2b + l * 128);
    }

    // head: out = x @ headW + headb   [768, 8192]
    gemm64<0><<<dim3(8192 / 64, 768 / 64), 256>>>(
        xp, headW, headb, out, 128, 128, 8192, 8192);
}

// round 2
// speedup vs baseline: 2.1774x; 2.1774x over previous
#include <cuda_runtime.h>
#include <math.h>
#include <stdint.h>

// Problem constants
#define BB 2
#define NN 384
#define DD 128
#define VV 8192
#define LL 2
#define NPAIR_B 73920        // N*(N+1)/2 per batch
#define NPAIR_T 147840       // both batches
#define PT 128               // pairs per tile
#define NTILES_MMA 1155      // 147840 / 128 exact

// ---------------- scratch (device globals; no allocation) ----------------
__device__ float g_x[BB * NN * DD];              // activations [B,N,128]
__device__ float g_a[BB * NN * 256];             // x @ W1[:128] + b1
__device__ float g_c[BB * NN * 256];             // x @ W1[128:]
__device__ float g_h[BB * NN * 512];             // FFN intermediate
__device__ float g_y[BB * NN * DD];              // FFN output
__device__ float g_p[(size_t)BB * NN * NN * DD]; // pair vectors (j<=i only)
__device__ float g_s[BB * NN * NN];              // pair norms

__device__ __forceinline__ float gelu_exact(float x) {
    return 0.5f * x * (1.0f + erff(x * 0.7071067811865475244f));
}

__device__ __forceinline__ uint32_t f2tf32(float x) {
    uint32_t r;
    asm("cvt.rna.tf32.f32 %0, %1;" : "=r"(r) : "f"(x));
    return r;
}

__device__ __forceinline__ void mma_tf32(float c[4],
                                         uint32_t a0, uint32_t a1, uint32_t a2, uint32_t a3,
                                         uint32_t b0, uint32_t b1) {
    asm volatile(
        "mma.sync.aligned.m16n8k8.row.col.f32.tf32.tf32.f32 "
        "{%0,%1,%2,%3}, {%4,%5,%6,%7}, {%8,%9}, {%0,%1,%2,%3};"
        : "+f"(c[0]), "+f"(c[1]), "+f"(c[2]), "+f"(c[3])
        : "r"(a0), "r"(a1), "r"(a2), "r"(a3), "r"(b0), "r"(b1));
}

// ---------------- embedding ----------------
__global__ void embed_kernel(const int* __restrict__ ids,
                             const float* __restrict__ emb,
                             const float* __restrict__ pos) {
    int t = blockIdx.x * blockDim.x + threadIdx.x;
    if (t >= BB * NN * DD) return;
    int d = t & (DD - 1);
    int bn = t >> 7;
    int n = bn % NN;
    g_x[t] = emb[ids[bn] * DD + d] + pos[n * DD + d];
}

// ---------------- generic 64x64x16 fp32 GEMM: C = act(A@W + bias) -------
template <int ACT>
__global__ __launch_bounds__(256) void gemm64(
    const float* __restrict__ A, const float* __restrict__ W,
    const float* __restrict__ bias, float* __restrict__ C,
    int K, int ldA, int ldW, int ldC) {
    __shared__ float As[16][64];
    __shared__ float Ws[16][64];
    const int bm = blockIdx.y * 64;
    const int bn = blockIdx.x * 64;
    const int tid = threadIdx.x;

    const int ar = tid >> 2;
    const int ak = (tid & 3) * 4;
    const int wk = tid >> 4;
    const int wn = (tid & 15) * 4;
    const int tm = (tid >> 4) * 4;
    const int tn = (tid & 15) * 4;

    float acc[4][4] = {};
    for (int k0 = 0; k0 < K; k0 += 16) {
        float4 av = *(const float4*)&A[(size_t)(bm + ar) * ldA + k0 + ak];
        As[ak + 0][ar] = av.x;
        As[ak + 1][ar] = av.y;
        As[ak + 2][ar] = av.z;
        As[ak + 3][ar] = av.w;
        *(float4*)&Ws[wk][wn] = *(const float4*)&W[(size_t)(k0 + wk) * ldW + bn + wn];
        __syncthreads();
#pragma unroll
        for (int k = 0; k < 16; k++) {
            float4 a = *(const float4*)&As[k][tm];
            float4 w = *(const float4*)&Ws[k][tn];
            acc[0][0] += a.x * w.x; acc[0][1] += a.x * w.y; acc[0][2] += a.x * w.z; acc[0][3] += a.x * w.w;
            acc[1][0] += a.y * w.x; acc[1][1] += a.y * w.y; acc[1][2] += a.y * w.z; acc[1][3] += a.y * w.w;
            acc[2][0] += a.z * w.x; acc[2][1] += a.z * w.y; acc[2][2] += a.z * w.z; acc[2][3] += a.z * w.w;
            acc[3][0] += a.w * w.x; acc[3][1] += a.w * w.y; acc[3][2] += a.w * w.z; acc[3][3] += a.w * w.w;
        }
        __syncthreads();
    }
    float4 bv = make_float4(0.f, 0.f, 0.f, 0.f);
    if (bias) bv = *(const float4*)&bias[bn + tn];
#pragma unroll
    for (int r = 0; r < 4; r++) {
        float4 o;
        o.x = acc[r][0] + bv.x;
        o.y = acc[r][1] + bv.y;
        o.z = acc[r][2] + bv.z;
        o.w = acc[r][3] + bv.w;
        if (ACT == 1) {
            o.x = gelu_exact(o.x); o.y = gelu_exact(o.y);
            o.z = gelu_exact(o.z); o.w = gelu_exact(o.w);
        }
        *(float4*)&C[(size_t)(bm + tm + r) * ldC + bn + tn] = o;
    }
}

// ---------------- pair kernel: tf32 tensor-core version ----------------
// Tile = 128 pairs. 8 warps in 4(M)x2(N) grid; warp tile 32x64.
// smem strides chosen for conflict-free mma fragment loads:
//   H1 panel [128][36], W panel [32][136], H2/P [128][132]
#define H1_STR 36
#define WP_STR 136
#define H2_STR 132
#define SM_H1 (128 * H1_STR)                  // 4608
#define SM_WP (32 * WP_STR)                   // 4352
#define SM_H2 (128 * H2_STR)                  // 16896
#define PM_SMEM_FLOATS (SM_H1 + SM_WP + SM_H2 + 256 + 384)
#define PM_SMEM_BYTES (PM_SMEM_FLOATS * 4)

__global__ __launch_bounds__(256, 2) void pair_mma(
    const float* __restrict__ W2, const float* __restrict__ b2,
    const float* __restrict__ W3, const float* __restrict__ b3) {
    extern __shared__ float sm[];
    float* H1s = sm;                      // [128][36]
    float* Wp = H1s + SM_H1;              // [32][136]
    float* H2s = Wp + SM_WP;              // [128][132]
    float* b2s = H2s + SM_H2;             // 128
    float* b3s = b2s + 128;               // 128
    int* rowA = (int*)(b3s + 128);        // 128
    int* rowC = rowA + 128;               // 128
    int* poff = rowC + 128;               // 128

    const int tid = threadIdx.x;
    const int lane = tid & 31;
    const int warp = tid >> 5;
    const int wm = warp >> 1;             // 0..3 -> M offset wm*32
    const int wn = warp & 1;              // 0..1 -> N offset wn*64
    const int lr = lane >> 2;             // 0..7
    const int lc = lane & 3;              // 0..3

    if (tid < 128) {
        b2s[tid] = b2[tid];
        b3s[tid] = b3[tid];
        // decode pair (b, i, j) for this tile row
        int g = blockIdx.x * PT + tid;
        int b = (g >= NPAIR_B) ? 1 : 0;
        int idx = g - b * NPAIR_B;
        int i = (int)((sqrtf(8.0f * (float)idx + 1.0f) - 1.0f) * 0.5f);
        while ((i + 1) * (i + 2) / 2 <= idx) ++i;
        while (i * (i + 1) / 2 > idx) --i;
        int j = idx - i * (i + 1) / 2;
        rowA[tid] = b * NN + i;
        rowC[tid] = b * NN + j;
        poff[tid] = (b * NN + i) * NN + j;
    }
    __syncthreads();

    float acc[2][8][4] = {};

    // ---------- GEMM1: H2 = gelu(gelu(a_i + c_j) @ W2 + b2) ----------
    for (int kc = 0; kc < 8; kc++) {
        const int k0 = kc * 32;
        // build H1 panel (tf32)
        for (int e = tid; e < 128 * 32; e += 256) {
            int r = e >> 5, kk = e & 31;
            float v = g_a[rowA[r] * 256 + k0 + kk] + g_c[rowC[r] * 256 + k0 + kk];
            H1s[r * H1_STR + kk] = __uint_as_float(f2tf32(gelu_exact(v)));
        }
        // load W2 panel (tf32)
        for (int e = tid; e < 32 * 128; e += 256) {
            int k = e >> 7, n = e & 127;
            Wp[k * WP_STR + n] = __uint_as_float(f2tf32(W2[(size_t)(k0 + k) * 128 + n]));
        }
        __syncthreads();
#pragma unroll
        for (int ks = 0; ks < 4; ks++) {
            const int kb = ks * 8;
            uint32_t a[2][4];
#pragma unroll
            for (int mt = 0; mt < 2; mt++) {
                int r0 = wm * 32 + mt * 16 + lr;
                a[mt][0] = __float_as_uint(H1s[r0 * H1_STR + kb + lc]);
                a[mt][1] = __float_as_uint(H1s[(r0 + 8) * H1_STR + kb + lc]);
                a[mt][2] = __float_as_uint(H1s[r0 * H1_STR + kb + 4 + lc]);
                a[mt][3] = __float_as_uint(H1s[(r0 + 8) * H1_STR + kb + 4 + lc]);
            }
#pragma unroll
            for (int nt = 0; nt < 8; nt++) {
                int n = wn * 64 + nt * 8 + lr;
                uint32_t b0 = __float_as_uint(Wp[(kb + lc) * WP_STR + n]);
                uint32_t b1 = __float_as_uint(Wp[(kb + 4 + lc) * WP_STR + n]);
                mma_tf32(acc[0][nt], a[0][0], a[0][1], a[0][2], a[0][3], b0, b1);
                mma_tf32(acc[1][nt], a[1][0], a[1][1], a[1][2], a[1][3], b0, b1);
            }
        }
        __syncthreads();
    }
    // epilogue 1: +b2, gelu, tf32 -> H2s
#pragma unroll
    for (int mt = 0; mt < 2; mt++) {
        int r0 = wm * 32 + mt * 16 + lr;
#pragma unroll
        for (int nt = 0; nt < 8; nt++) {
            int cb = wn * 64 + nt * 8 + 2 * lc;
            H2s[r0 * H2_STR + cb] = __uint_as_float(f2tf32(gelu_exact(acc[mt][nt][0] + b2s[cb])));
            H2s[r0 * H2_STR + cb + 1] = __uint_as_float(f2tf32(gelu_exact(acc[mt][nt][1] + b2s[cb + 1])));
            H2s[(r0 + 8) * H2_STR + cb] = __uint_as_float(f2tf32(gelu_exact(acc[mt][nt][2] + b2s[cb])));
            H2s[(r0 + 8) * H2_STR + cb + 1] = __uint_as_float(f2tf32(gelu_exact(acc[mt][nt][3] + b2s[cb + 1])));
        }
    }
    __syncthreads();

    // ---------- GEMM2: P = H2 @ W3 + b3 ----------
#pragma unroll
    for (int mt = 0; mt < 2; mt++)
#pragma unroll
        for (int nt = 0; nt < 8; nt++)
#pragma unroll
            for (int q = 0; q < 4; q++) acc[mt][nt][q] = 0.f;

    for (int kc = 0; kc < 4; kc++) {
        const int k0 = kc * 32;
        for (int e = tid; e < 32 * 128; e += 256) {
            int k = e >> 7, n = e & 127;
            Wp[k * WP_STR + n] = __uint_as_float(f2tf32(W3[(size_t)(k0 + k) * 128 + n]));
        }
        __syncthreads();
#pragma unroll
        for (int ks = 0; ks < 4; ks++) {
            const int kb = ks * 8;
            uint32_t a[2][4];
#pragma unroll
            for (int mt = 0; mt < 2; mt++) {
                int r0 = wm * 32 + mt * 16 + lr;
                a[mt][0] = __float_as_uint(H2s[r0 * H2_STR + k0 + kb + lc]);
                a[mt][1] = __float_as_uint(H2s[(r0 + 8) * H2_STR + k0 + kb + lc]);
                a[mt][2] = __float_as_uint(H2s[r0 * H2_STR + k0 + kb + 4 + lc]);
                a[mt][3] = __float_as_uint(H2s[(r0 + 8) * H2_STR + k0 + kb + 4 + lc]);
            }
#pragma unroll
            for (int nt = 0; nt < 8; nt++) {
                int n = wn * 64 + nt * 8 + lr;
                uint32_t b0 = __float_as_uint(Wp[(kb + lc) * WP_STR + n]);
                uint32_t b1 = __float_as_uint(Wp[(kb + 4 + lc) * WP_STR + n]);
                mma_tf32(acc[0][nt], a[0][0], a[0][1], a[0][2], a[0][3], b0, b1);
                mma_tf32(acc[1][nt], a[1][0], a[1][1], a[1][2], a[1][3], b0, b1);
            }
        }
        __syncthreads();
    }
    // epilogue 2: +b3 -> P back into H2s (full fp32)
#pragma unroll
    for (int mt = 0; mt < 2; mt++) {
        int r0 = wm * 32 + mt * 16 + lr;
#pragma unroll
        for (int nt = 0; nt < 8; nt++) {
            int cb = wn * 64 + nt * 8 + 2 * lc;
            H2s[r0 * H2_STR + cb] = acc[mt][nt][0] + b3s[cb];
            H2s[r0 * H2_STR + cb + 1] = acc[mt][nt][1] + b3s[cb + 1];
            H2s[(r0 + 8) * H2_STR + cb] = acc[mt][nt][2] + b3s[cb];
            H2s[(r0 + 8) * H2_STR + cb + 1] = acc[mt][nt][3] + b3s[cb + 1];
        }
    }
    __syncthreads();

    // writeout: each pair of threads handles one pair-row (128 floats)
    {
        int r = tid >> 1, half = tid & 1;
        const float* src = H2s + r * H2_STR + half * 64;
        float* dst = g_p + (size_t)poff[r] * DD + half * 64;
        float ss = 0.f;
#pragma unroll
        for (int q = 0; q < 64; q += 4) {
            float4 v = *(const float4*)(src + q);
            *(float4*)(dst + q) = v;
            ss += v.x * v.x + v.y * v.y + v.z * v.z + v.w * v.w;
        }
        ss += __shfl_xor_sync(0xffffffffu, ss, 1);
        if (!half) g_s[poff[r]] = sqrtf(fmaxf(ss, 1e-30f));
    }
}

// ---------------- block-of-128 reductions ----------------
__device__ __forceinline__ float blockSum128(float v, float* red) {
    int tid = threadIdx.x;
    red[tid] = v;
    __syncthreads();
    for (int s = 64; s; s >>= 1) {
        if (tid < s) red[tid] += red[tid + s];
        __syncthreads();
    }
    float r = red[0];
    __syncthreads();
    return r;
}
__device__ __forceinline__ float blockMax128(float v, float* red) {
    int tid = threadIdx.x;
    red[tid] = v;
    __syncthreads();
    for (int s = 64; s; s >>= 1) {
        if (tid < s) red[tid] = fmaxf(red[tid], red[tid + s]);
        __syncthreads();
    }
    float r = red[0];
    __syncthreads();
    return r;
}

// ---------------- phase B: softmax over norms + weighted sum + residual + LN
__global__ __launch_bounds__(128) void pair_reduce_ln(
    const float* __restrict__ lng, const float* __restrict__ lnb) {
    __shared__ float red[128];
    const int bi = blockIdx.x;          // b*NN + i
    const int i = bi % NN;
    const int tid = threadIdx.x;
    const int np = i + 1;
    const float* srow = g_s + (size_t)bi * NN;

    float lm = -1e30f;
    for (int j = tid; j < np; j += 128) lm = fmaxf(lm, srow[j]);
    float m = blockMax128(lm, red);

    const float* prow = g_p + (size_t)bi * NN * DD;
    float acc = 0.f, den = 0.f;
#pragma unroll 4
    for (int j = 0; j < np; j++) {
        float w = expf(srow[j] - m);
        den += w;
        acc += w * prow[(size_t)j * DD + tid];
    }
    float v = g_x[bi * DD + tid] + acc / den;

    float mean = blockSum128(v, red) * (1.0f / DD);
    float dv = v - mean;
    float var = blockSum128(dv * dv, red) * (1.0f / DD);
    g_x[bi * DD + tid] = dv * rsqrtf(var + 1e-5f) * lng[tid] + lnb[tid];
}

// ---------------- FFN residual + LN ----------------
__global__ __launch_bounds__(128) void add_ln(
    const float* __restrict__ lng, const float* __restrict__ lnb) {
    __shared__ float red[128];
    const int bi = blockIdx.x;
    const int tid = threadIdx.x;
    float v = g_x[bi * DD + tid] + g_y[bi * DD + tid];
    float mean = blockSum128(v, red) * (1.0f / DD);
    float dv = v - mean;
    float var = blockSum128(dv * dv, red) * (1.0f / DD);
    g_x[bi * DD + tid] = dv * rsqrtf(var + 1e-5f) * lng[tid] + lnb[tid];
}

// ---------------- launcher ----------------
extern "C" void kernel_launch(void* const* d_in, const int* in_sizes, int n_in,
                              void* d_out, int out_size) {
    const int* ids = (const int*)d_in[0];
    const float* embw = (const float*)d_in[1];
    const float* pos = (const float*)d_in[2];
    const float* pW1 = (const float*)d_in[3];
    const float* pb1 = (const float*)d_in[4];
    const float* pW2 = (const float*)d_in[5];
    const float* pb2 = (const float*)d_in[6];
    const float* pW3 = (const float*)d_in[7];
    const float* pb3 = (const float*)d_in[8];
    const float* ln1g = (const float*)d_in[9];
    const float* ln1b = (const float*)d_in[10];
    const float* fW1 = (const float*)d_in[11];
    const float* fb1 = (const float*)d_in[12];
    const float* fW2 = (const float*)d_in[13];
    const float* fb2 = (const float*)d_in[14];
    const float* ln2g = (const float*)d_in[15];
    const float* ln2b = (const float*)d_in[16];
    const float* headW = (const float*)d_in[17];
    const float* headb = (const float*)d_in[18];
    float* out = (float*)d_out;

    static int init_done = 0;
    cudaFuncSetAttribute(pair_mma, cudaFuncAttributeMaxDynamicSharedMemorySize,
                         PM_SMEM_BYTES);
    (void)init_done;

    float *xp, *ap, *cp, *hp, *yp;
    cudaGetSymbolAddress((void**)&xp, g_x);
    cudaGetSymbolAddress((void**)&ap, g_a);
    cudaGetSymbolAddress((void**)&cp, g_c);
    cudaGetSymbolAddress((void**)&hp, g_h);
    cudaGetSymbolAddress((void**)&yp, g_y);

    embed_kernel<<<(BB * NN * DD + 255) / 256, 256>>>(ids, embw, pos);

    for (int l = 0; l < LL; l++) {
        // A = x @ W1[:128,:] + b1   -> g_a [768,256]
        gemm64<0><<<dim3(256 / 64, 768 / 64), 256>>>(
            xp, pW1 + (size_t)l * 256 * 256, pb1 + l * 256, ap, 128, 128, 256, 256);
        // C = x @ W1[128:,:]        -> g_c [768,256]
        gemm64<0><<<dim3(256 / 64, 768 / 64), 256>>>(
            xp, pW1 + (size_t)l * 256 * 256 + 128 * 256, nullptr, cp, 128, 128, 256, 256);
        // pair vectors + norms (tensor cores, tf32)
        pair_mma<<<NTILES_MMA, 256, PM_SMEM_BYTES>>>(
            pW2 + (size_t)l * 256 * 128, pb2 + l * 128,
            pW3 + (size_t)l * 128 * 128, pb3 + l * 128);
        // softmax-weighted reduce + residual + LN1
        pair_reduce_ln<<<BB * NN, 128>>>(ln1g + l * 128, ln1b + l * 128);
        // FFN
        gemm64<1><<<dim3(512 / 64, 768 / 64), 256>>>(
            xp, fW1 + (size_t)l * 128 * 512, fb1 + l * 512, hp, 128, 128, 512, 512);
        gemm64<0><<<dim3(128 / 64, 768 / 64), 256>>>(
            hp, fW2 + (size_t)l * 512 * 128, fb2 + l * 128, yp, 512, 512, 128, 128);
        add_ln<<<BB * NN, 128>>>(ln2g + l * 128, ln2b + l * 128);
    }

    // head: out = x @ headW + headb   [768, 8192]
    gemm64<0><<<dim3(8192 / 64, 768 / 64), 256>>>(
        xp, headW, headb, out, 128, 128, 8192, 8192);
}

// round 3
// speedup vs baseline: 3.5971x; 1.6520x over previous
#include <cuda_runtime.h>
#include <cuda_fp16.h>
#include <math.h>
#include <stdint.h>

// Problem constants
#define BB 2
#define NN 384
#define DD 128
#define VV 8192
#define LL 2
#define NPAIR_B 73920        // N*(N+1)/2 per batch
#define NPAIR_T 147840       // both batches
#define PT 128               // pairs per tile
#define NTILES_MMA 1155      // 147840 / 128 exact

// ---------------- scratch (device globals; no allocation) ----------------
__device__ float g_x[BB * NN * DD];
__device__ float g_a[BB * NN * 256];
__device__ float g_c[BB * NN * 256];
__device__ float g_h[BB * NN * 512];
__device__ float g_y[BB * NN * DD];
__device__ float g_p[(size_t)BB * NN * NN * DD];
__device__ float g_s[BB * NN * NN];

// exact gelu via A&S 7.1.26 erf (max abs err 1.5e-7), branchless
__device__ __forceinline__ float gelu_fast(float x) {
    float y = fabsf(x) * 0.70710678118654752f;
    float q = fmaf(0.3275911f, y, 1.0f);
    float t;
    asm("rcp.approx.f32 %0, %1;" : "=f"(t) : "f"(q));
    float p = fmaf(fmaf(fmaf(fmaf(1.061405429f, t, -1.453152027f), t,
                             1.421413741f), t, -0.284496736f), t, 0.254829592f) * t;
    float e = __expf(-y * y);
    float erf_abs = fmaf(-p, e, 1.0f);
    float s = copysignf(erf_abs, x);
    return 0.5f * x * (1.0f + s);
}

__device__ __forceinline__ void ldsm4(uint32_t* r, uint32_t addr) {
    asm volatile("ldmatrix.sync.aligned.m8n8.x4.shared.b16 {%0,%1,%2,%3}, [%4];"
                 : "=r"(r[0]), "=r"(r[1]), "=r"(r[2]), "=r"(r[3]) : "r"(addr));
}
__device__ __forceinline__ void ldsm4t(uint32_t* r, uint32_t addr) {
    asm volatile("ldmatrix.sync.aligned.m8n8.x4.trans.shared.b16 {%0,%1,%2,%3}, [%4];"
                 : "=r"(r[0]), "=r"(r[1]), "=r"(r[2]), "=r"(r[3]) : "r"(addr));
}
__device__ __forceinline__ void mma_f16(float c[4], const uint32_t a[4],
                                        uint32_t b0, uint32_t b1) {
    asm volatile(
        "mma.sync.aligned.m16n8k16.row.col.f32.f16.f16.f32 "
        "{%0,%1,%2,%3}, {%4,%5,%6,%7}, {%8,%9}, {%0,%1,%2,%3};"
        : "+f"(c[0]), "+f"(c[1]), "+f"(c[2]), "+f"(c[3])
        : "r"(a[0]), "r"(a[1]), "r"(a[2]), "r"(a[3]), "r"(b0), "r"(b1));
}

// ---------------- embedding ----------------
__global__ void embed_kernel(const int* __restrict__ ids,
                             const float* __restrict__ emb,
                             const float* __restrict__ pos) {
    int t = blockIdx.x * blockDim.x + threadIdx.x;
    if (t >= BB * NN * DD) return;
    int d = t & (DD - 1);
    int bn = t >> 7;
    int n = bn % NN;
    g_x[t] = emb[ids[bn] * DD + d] + pos[n * DD + d];
}

// ---------------- generic 64x64x16 fp32 GEMM ----------------
template <int ACT>
__global__ __launch_bounds__(256) void gemm64(
    const float* __restrict__ A, const float* __restrict__ W,
    const float* __restrict__ bias, float* __restrict__ C,
    int K, int ldA, int ldW, int ldC) {
    __shared__ float As[16][64];
    __shared__ float Ws[16][64];
    const int bm = blockIdx.y * 64;
    const int bn = blockIdx.x * 64;
    const int tid = threadIdx.x;

    const int ar = tid >> 2;
    const int ak = (tid & 3) * 4;
    const int wk = tid >> 4;
    const int wn = (tid & 15) * 4;
    const int tm = (tid >> 4) * 4;
    const int tn = (tid & 15) * 4;

    float acc[4][4] = {};
    for (int k0 = 0; k0 < K; k0 += 16) {
        float4 av = *(const float4*)&A[(size_t)(bm + ar) * ldA + k0 + ak];
        As[ak + 0][ar] = av.x;
        As[ak + 1][ar] = av.y;
        As[ak + 2][ar] = av.z;
        As[ak + 3][ar] = av.w;
        *(float4*)&Ws[wk][wn] = *(const float4*)&W[(size_t)(k0 + wk) * ldW + bn + wn];
        __syncthreads();
#pragma unroll
        for (int k = 0; k < 16; k++) {
            float4 a = *(const float4*)&As[k][tm];
            float4 w = *(const float4*)&Ws[k][tn];
            acc[0][0] += a.x * w.x; acc[0][1] += a.x * w.y; acc[0][2] += a.x * w.z; acc[0][3] += a.x * w.w;
            acc[1][0] += a.y * w.x; acc[1][1] += a.y * w.y; acc[1][2] += a.y * w.z; acc[1][3] += a.y * w.w;
            acc[2][0] += a.z * w.x; acc[2][1] += a.z * w.y; acc[2][2] += a.z * w.z; acc[2][3] += a.z * w.w;
            acc[3][0] += a.w * w.x; acc[3][1] += a.w * w.y; acc[3][2] += a.w * w.z; acc[3][3] += a.w * w.w;
        }
        __syncthreads();
    }
    float4 bv = make_float4(0.f, 0.f, 0.f, 0.f);
    if (bias) bv = *(const float4*)&bias[bn + tn];
#pragma unroll
    for (int r = 0; r < 4; r++) {
        float4 o;
        o.x = acc[r][0] + bv.x;
        o.y = acc[r][1] + bv.y;
        o.z = acc[r][2] + bv.z;
        o.w = acc[r][3] + bv.w;
        if (ACT == 1) {
            o.x = gelu_fast(o.x); o.y = gelu_fast(o.y);
            o.z = gelu_fast(o.z); o.w = gelu_fast(o.w);
        }
        *(float4*)&C[(size_t)(bm + tm + r) * ldC + bn + tn] = o;
    }
}

// ---------------- pair kernel: fp16 mma + ldmatrix ----------------
// strides in halves; chosen so 8 ldmatrix row-addresses spread all banks
#define SA 72     // H1 [128][64]+pad      (144B rows; 144%128=16)
#define SBW 136   // W  [64][128]+pad      (272B rows; %128=16)
#define SH 136    // H2 [128][128]+pad
#define SPF 132   // Pf fp32 stride (floats)

#define OFF_H1 0
#define OFF_W 18432
#define OFF_H2 35840
#define OFF_B2 70656
#define OFF_B3 71168
#define OFF_RA 71680
#define OFF_RC 72192
#define OFF_PO 72704
#define PM_SMEM_BYTES 73216

__global__ __launch_bounds__(256, 2) void pair_mma(
    const float* __restrict__ W2, const float* __restrict__ b2,
    const float* __restrict__ W3, const float* __restrict__ b3) {
    extern __shared__ char smc[];
    __half* H1s = (__half*)(smc + OFF_H1);
    __half* WTs = (__half*)(smc + OFF_W);
    __half* H2s = (__half*)(smc + OFF_H2);
    float* Pf = (float*)smc;                 // epilogue-2 only (overlaps all above)
    float* b2s = (float*)(smc + OFF_B2);
    float* b3s = (float*)(smc + OFF_B3);
    int* rowA = (int*)(smc + OFF_RA);
    int* rowC = (int*)(smc + OFF_RC);
    int* poff = (int*)(smc + OFF_PO);

    const int tid = threadIdx.x;
    const int lane = tid & 31;
    const int warp = tid >> 5;
    const int wm = warp >> 1;      // 0..3 -> M base wm*32
    const int wn = warp & 1;       // 0..1 -> N base wn*64
    const int lr = lane >> 2;      // 0..7
    const int lc = lane & 3;       // 0..3

    // ldmatrix lane offsets: g = lane>>3
    const int lrow = (lane & 7) + ((lane >> 3) & 1) * 8; // row-in-16
    const int lcol = (lane >> 4) * 8;                    // col-in-16 (0/8)

    const uint32_t sb = (uint32_t)__cvta_generic_to_shared(smc);
    const uint32_t h1_lane = sb + OFF_H1 + (uint32_t)(lrow * SA + lcol) * 2;
    const uint32_t w_lane = sb + OFF_W + (uint32_t)(lrow * SBW + lcol) * 2;
    const uint32_t h2_lane = sb + OFF_H2 + (uint32_t)(lrow * SH + lcol) * 2;

    if (tid < 128) {
        b2s[tid] = b2[tid];
        b3s[tid] = b3[tid];
        int g = blockIdx.x * PT + tid;
        int b = (g >= NPAIR_B) ? 1 : 0;
        int idx = g - b * NPAIR_B;
        int i = (int)((sqrtf(8.0f * (float)idx + 1.0f) - 1.0f) * 0.5f);
        while ((i + 1) * (i + 2) / 2 <= idx) ++i;
        while (i * (i + 1) / 2 > idx) --i;
        int j = idx - i * (i + 1) / 2;
        rowA[tid] = b * NN + i;
        rowC[tid] = b * NN + j;
        poff[tid] = (b * NN + i) * NN + j;
    }
    __syncthreads();

    float acc[2][8][4] = {};
    uint32_t af[2][4];
    uint32_t bf[4];

    // ---------- GEMM1: acc = gelu(a_i + c_j) @ W2  (K = 256, 4 chunks of 64)
    for (int kc = 0; kc < 4; kc++) {
        const int k0 = kc * 64;
        // build H1 chunk [128][64] as half (vectorized)
        for (int e = tid; e < 128 * 16; e += 256) {
            int r = e >> 4, c4 = e & 15;
            const float4 av = *(const float4*)&g_a[rowA[r] * 256 + k0 + c4 * 4];
            const float4 cv = *(const float4*)&g_c[rowC[r] * 256 + k0 + c4 * 4];
            __half2 lo = __floats2half2_rn(gelu_fast(av.x + cv.x), gelu_fast(av.y + cv.y));
            __half2 hi = __floats2half2_rn(gelu_fast(av.z + cv.z), gelu_fast(av.w + cv.w));
            __half2* d = (__half2*)(H1s + r * SA + c4 * 4);
            d[0] = lo; d[1] = hi;
        }
        // load W2 chunk [64 k][128 n] as half (natural layout)
        for (int e = tid; e < 64 * 32; e += 256) {
            int k = e >> 5, n4 = e & 31;
            const float4 wv = *(const float4*)&W2[(size_t)(k0 + k) * 128 + n4 * 4];
            __half2* d = (__half2*)(WTs + k * SBW + n4 * 4);
            d[0] = __floats2half2_rn(wv.x, wv.y);
            d[1] = __floats2half2_rn(wv.z, wv.w);
        }
        __syncthreads();
#pragma unroll
        for (int ks = 0; ks < 4; ks++) {
            const int kb = ks * 16;
#pragma unroll
            for (int mt = 0; mt < 2; mt++)
                ldsm4(af[mt], h1_lane + (uint32_t)((wm * 32 + mt * 16) * SA + kb) * 2);
#pragma unroll
            for (int bt = 0; bt < 4; bt++) {
                ldsm4t(bf, w_lane + (uint32_t)(kb * SBW + wn * 64 + bt * 16) * 2);
                mma_f16(acc[0][2 * bt], af[0], bf[0], bf[1]);
                mma_f16(acc[1][2 * bt], af[1], bf[0], bf[1]);
                mma_f16(acc[0][2 * bt + 1], af[0], bf[2], bf[3]);
                mma_f16(acc[1][2 * bt + 1], af[1], bf[2], bf[3]);
            }
        }
        __syncthreads();
    }
    // epilogue 1: +b2, gelu, half -> H2s
#pragma unroll
    for (int mt = 0; mt < 2; mt++) {
        int r0 = wm * 32 + mt * 16 + lr;
#pragma unroll
        for (int nt = 0; nt < 8; nt++) {
            int cb = wn * 64 + nt * 8 + 2 * lc;
            float bx = b2s[cb], by = b2s[cb + 1];
            *(__half2*)(H2s + r0 * SH + cb) =
                __floats2half2_rn(gelu_fast(acc[mt][nt][0] + bx), gelu_fast(acc[mt][nt][1] + by));
            *(__half2*)(H2s + (r0 + 8) * SH + cb) =
                __floats2half2_rn(gelu_fast(acc[mt][nt][2] + bx), gelu_fast(acc[mt][nt][3] + by));
        }
    }

    // ---------- GEMM2: P = H2 @ W3 + b3  (K = 128, 2 chunks of 64)
#pragma unroll
    for (int mt = 0; mt < 2; mt++)
#pragma unroll
        for (int nt = 0; nt < 8; nt++)
#pragma unroll
            for (int q = 0; q < 4; q++) acc[mt][nt][q] = 0.f;

    for (int kc = 0; kc < 2; kc++) {
        const int k0 = kc * 64;
        for (int e = tid; e < 64 * 32; e += 256) {
            int k = e >> 5, n4 = e & 31;
            const float4 wv = *(const float4*)&W3[(size_t)(k0 + k) * 128 + n4 * 4];
            __half2* d = (__half2*)(WTs + k * SBW + n4 * 4);
            d[0] = __floats2half2_rn(wv.x, wv.y);
            d[1] = __floats2half2_rn(wv.z, wv.w);
        }
        __syncthreads();   // also orders epilogue-1 H2s writes before frag reads
#pragma unroll
        for (int ks = 0; ks < 4; ks++) {
            const int kbl = ks * 16;
            const int kbg = k0 + kbl;
#pragma unroll
            for (int mt = 0; mt < 2; mt++)
                ldsm4(af[mt], h2_lane + (uint32_t)((wm * 32 + mt * 16) * SH + kbg) * 2);
#pragma unroll
            for (int bt = 0; bt < 4; bt++) {
                ldsm4t(bf, w_lane + (uint32_t)(kbl * SBW + wn * 64 + bt * 16) * 2);
                mma_f16(acc[0][2 * bt], af[0], bf[0], bf[1]);
                mma_f16(acc[1][2 * bt], af[1], bf[0], bf[1]);
                mma_f16(acc[0][2 * bt + 1], af[0], bf[2], bf[3]);
                mma_f16(acc[1][2 * bt + 1], af[1], bf[2], bf[3]);
            }
        }
        __syncthreads();
    }

    // epilogue 2: +b3 -> Pf (fp32, overlaps dead H1/W/H2 buffers)
#pragma unroll
    for (int mt = 0; mt < 2; mt++) {
        int r0 = wm * 32 + mt * 16 + lr;
#pragma unroll
        for (int nt = 0; nt < 8; nt++) {
            int cb = wn * 64 + nt * 8 + 2 * lc;
            float bx = b3s[cb], by = b3s[cb + 1];
            *(float2*)(Pf + r0 * SPF + cb) =
                make_float2(acc[mt][nt][0] + bx, acc[mt][nt][1] + by);
            *(float2*)(Pf + (r0 + 8) * SPF + cb) =
                make_float2(acc[mt][nt][2] + bx, acc[mt][nt][3] + by);
        }
    }
    __syncthreads();

    // writeout: 2 threads per pair-row; float4 stores + norm
    {
        int r = tid >> 1, half = tid & 1;
        const float* src = Pf + r * SPF + half * 64;
        float* dst = g_p + (size_t)poff[r] * DD + half * 64;
        float ss = 0.f;
#pragma unroll
        for (int q = 0; q < 64; q += 4) {
            float4 v = *(const float4*)(src + q);
            *(float4*)(dst + q) = v;
            ss += v.x * v.x + v.y * v.y + v.z * v.z + v.w * v.w;
        }
        ss += __shfl_xor_sync(0xffffffffu, ss, 1);
        if (!half) g_s[poff[r]] = sqrtf(fmaxf(ss, 1e-30f));
    }
}

// ---------------- block reductions ----------------
__device__ __forceinline__ float blockSum128(float v, float* red) {
    int tid = threadIdx.x;
    red[tid] = v;
    __syncthreads();
    for (int s = 64; s; s >>= 1) {
        if (tid < s) red[tid] += red[tid + s];
        __syncthreads();
    }
    float r = red[0];
    __syncthreads();
    return r;
}
__device__ __forceinline__ float blockMax128(float v, float* red) {
    int tid = threadIdx.x;
    red[tid] = v;
    __syncthreads();
    for (int s = 64; s; s >>= 1) {
        if (tid < s) red[tid] = fmaxf(red[tid], red[tid + s]);
        __syncthreads();
    }
    float r = red[0];
    __syncthreads();
    return r;
}

// ---------------- phase B: softmax + weighted sum + residual + LN ----------
__global__ __launch_bounds__(128) void pair_reduce_ln(
    const float* __restrict__ lng, const float* __restrict__ lnb) {
    __shared__ float red[128];
    __shared__ float ws[NN];
    const int bi = blockIdx.x;
    const int i = bi % NN;
    const int tid = threadIdx.x;
    const int np = i + 1;
    const float* srow = g_s + (size_t)bi * NN;

    float lm = -1e30f;
    for (int j = tid; j < np; j += 128) lm = fmaxf(lm, srow[j]);
    float m = blockMax128(lm, red);

    float dsum = 0.f;
    for (int j = tid; j < np; j += 128) {
        float w = expf(srow[j] - m);
        ws[j] = w;
        dsum += w;
    }
    float den = blockSum128(dsum, red);   // includes barrier -> ws visible

    const float* prow = g_p + (size_t)bi * NN * DD;
    float acc = 0.f;
#pragma unroll 4
    for (int j = 0; j < np; j++) acc += ws[j] * prow[(size_t)j * DD + tid];

    float v = g_x[bi * DD + tid] + acc / den;
    float mean = blockSum128(v, red) * (1.0f / DD);
    float dv = v - mean;
    float var = blockSum128(dv * dv, red) * (1.0f / DD);
    g_x[bi * DD + tid] = dv * rsqrtf(var + 1e-5f) * lng[tid] + lnb[tid];
}

// ---------------- FFN residual + LN ----------------
__global__ __launch_bounds__(128) void add_ln(
    const float* __restrict__ lng, const float* __restrict__ lnb) {
    __shared__ float red[128];
    const int bi = blockIdx.x;
    const int tid = threadIdx.x;
    float v = g_x[bi * DD + tid] + g_y[bi * DD + tid];
    float mean = blockSum128(v, red) * (1.0f / DD);
    float dv = v - mean;
    float var = blockSum128(dv * dv, red) * (1.0f / DD);
    g_x[bi * DD + tid] = dv * rsqrtf(var + 1e-5f) * lng[tid] + lnb[tid];
}

// ---------------- launcher ----------------
extern "C" void kernel_launch(void* const* d_in, const int* in_sizes, int n_in,
                              void* d_out, int out_size) {
    const int* ids = (const int*)d_in[0];
    const float* embw = (const float*)d_in[1];
    const float* pos = (const float*)d_in[2];
    const float* pW1 = (const float*)d_in[3];
    const float* pb1 = (const float*)d_in[4];
    const float* pW2 = (const float*)d_in[5];
    const float* pb2 = (const float*)d_in[6];
    const float* pW3 = (const float*)d_in[7];
    const float* pb3 = (const float*)d_in[8];
    const float* ln1g = (const float*)d_in[9];
    const float* ln1b = (const float*)d_in[10];
    const float* fW1 = (const float*)d_in[11];
    const float* fb1 = (const float*)d_in[12];
    const float* fW2 = (const float*)d_in[13];
    const float* fb2 = (const float*)d_in[14];
    const float* ln2g = (const float*)d_in[15];
    const float* ln2b = (const float*)d_in[16];
    const float* headW = (const float*)d_in[17];
    const float* headb = (const float*)d_in[18];
    float* out = (float*)d_out;

    cudaFuncSetAttribute(pair_mma, cudaFuncAttributeMaxDynamicSharedMemorySize,
                         PM_SMEM_BYTES);

    float *xp, *ap, *cp, *hp, *yp;
    cudaGetSymbolAddress((void**)&xp, g_x);
    cudaGetSymbolAddress((void**)&ap, g_a);
    cudaGetSymbolAddress((void**)&cp, g_c);
    cudaGetSymbolAddress((void**)&hp, g_h);
    cudaGetSymbolAddress((void**)&yp, g_y);

    embed_kernel<<<(BB * NN * DD + 255) / 256, 256>>>(ids, embw, pos);

    for (int l = 0; l < LL; l++) {
        gemm64<0><<<dim3(256 / 64, 768 / 64), 256>>>(
            xp, pW1 + (size_t)l * 256 * 256, pb1 + l * 256, ap, 128, 128, 256, 256);
        gemm64<0><<<dim3(256 / 64, 768 / 64), 256>>>(
            xp, pW1 + (size_t)l * 256 * 256 + 128 * 256, nullptr, cp, 128, 128, 256, 256);
        pair_mma<<<NTILES_MMA, 256, PM_SMEM_BYTES>>>(
            pW2 + (size_t)l * 256 * 128, pb2 + l * 128,
            pW3 + (size_t)l * 128 * 128, pb3 + l * 128);
        pair_reduce_ln<<<BB * NN, 128>>>(ln1g + l * 128, ln1b + l * 128);
        gemm64<1><<<dim3(512 / 64, 768 / 64), 256>>>(
            xp, fW1 + (size_t)l * 128 * 512, fb1 + l * 512, hp, 128, 128, 512, 512);
        gemm64<0><<<dim3(128 / 64, 768 / 64), 256>>>(
            hp, fW2 + (size_t)l * 512 * 128, fb2 + l * 128, yp, 512, 512, 128, 128);
        add_ln<<<BB * NN, 128>>>(ln2g + l * 128, ln2b + l * 128);
    }

    gemm64<0><<<dim3(8192 / 64, 768 / 64), 256>>>(
        xp, headW, headb, out, 128, 128, 8192, 8192);
}